// round 1
// baseline (speedup 1.0000x reference)
#include <cuda_runtime.h>

// out[b][o] = sum_i x[b][i] * W[o][i] + bias[o]
// x: (1048576, 128) f32, W: (128, 128) f32 row-major (out, in), b: (128,1) f32.
//
// Round-1 baseline: FP32 FFMA, compute-bound (~34 TF/s FP32 ceiling -> ~2 ms).
// CTA tile: 64 rows x 128 cols, K=128 resident.
//   smem: ws[k][o] (W transposed, row padded to 132 floats, 16B-aligned rows)
//         xs[r][k] (x tile)
//   thread (256/CTA): 8 rows x 4 cols micro-tile -> 32 independent accumulators.

#define K        128
#define NOUT     128
#define TILE_ROWS 64
#define THREADS  256
#define WPAD     132   // 132*4 = 528 B row stride; 528 = 16*33 -> float4-aligned rows

__global__ __launch_bounds__(THREADS, 1)
void linear128_fp32_kernel(const float* __restrict__ x,
                           const float* __restrict__ W,
                           const float* __restrict__ bias,
                           float* __restrict__ out)
{
    extern __shared__ float smem[];
    float* ws = smem;              // ws[i * WPAD + o] = W[o][i]   (K x NOUT, padded)
    float* xs = smem + K * WPAD;   // xs[r * K + k]                (TILE_ROWS x K)

    const int tid = threadIdx.x;
    const size_t row_base = (size_t)blockIdx.x * TILE_ROWS;

    // ---- Stage W transposed into smem (coalesced global read; padded smem write,
    //      worst case 4-way bank conflict, one-time cost ~hundreds of cycles) ----
    for (int idx = tid; idx < NOUT * K; idx += THREADS) {
        int o = idx >> 7;      // / 128
        int i = idx & 127;     // % 128
        ws[i * WPAD + o] = W[idx];
    }

    // ---- Stage x tile via float4 (fully coalesced) ----
    {
        const float4* xg = (const float4*)(x + row_base * K);
        float4* xs4 = (float4*)xs;
        #pragma unroll 4
        for (int idx = tid; idx < TILE_ROWS * (K / 4); idx += THREADS) {
            xs4[idx] = xg[idx];
        }
    }
    __syncthreads();

    // thread -> micro-tile mapping:
    //   lanes within a warp cover 32 col-groups (broadcast-friendly xs reads),
    //   warps cover 8 row-groups.
    const int cg = tid & 31;   // col group: cols 4*cg .. 4*cg+3
    const int rg = tid >> 5;   // row group: rows 8*rg .. 8*rg+7
    const int c0 = cg * 4;
    const int r0 = rg * 8;

    float acc[8][4];
    #pragma unroll
    for (int r = 0; r < 8; r++)
        #pragma unroll
        for (int c = 0; c < 4; c++) acc[r][c] = 0.0f;

    // ---- Main K loop ----
    // Per k: 1x LDS.128 for w (contiguous across lanes -> conflict-free),
    //        8 broadcast xs loads (same address across warp),
    //        32 FFMA. Unroll 4 lets ptxas fuse xs loads into LDS.128 per row.
    #pragma unroll 4
    for (int k = 0; k < K; k++) {
        const float4 wv = *(const float4*)(ws + k * WPAD + c0);
        float xv[8];
        #pragma unroll
        for (int r = 0; r < 8; r++) xv[r] = xs[(r0 + r) * K + k];
        #pragma unroll
        for (int r = 0; r < 8; r++) {
            acc[r][0] = fmaf(xv[r], wv.x, acc[r][0]);
            acc[r][1] = fmaf(xv[r], wv.y, acc[r][1]);
            acc[r][2] = fmaf(xv[r], wv.z, acc[r][2]);
            acc[r][3] = fmaf(xv[r], wv.w, acc[r][3]);
        }
    }

    // ---- Bias + store (float4, contiguous 512B per row across each warp) ----
    const float4 bv = *(const float4*)(bias + c0);
    float* og = out + (row_base + (size_t)r0) * NOUT + c0;
    #pragma unroll
    for (int r = 0; r < 8; r++) {
        float4 ov;
        ov.x = acc[r][0] + bv.x;
        ov.y = acc[r][1] + bv.y;
        ov.z = acc[r][2] + bv.z;
        ov.w = acc[r][3] + bv.w;
        *(float4*)(og + (size_t)r * NOUT) = ov;
    }
}

extern "C" void kernel_launch(void* const* d_in, const int* in_sizes, int n_in,
                              void* d_out, int out_size)
{
    const float* x    = (const float*)d_in[0];  // (BATCH, 128)
    const float* W    = (const float*)d_in[1];  // (128, 128)
    const float* bias = (const float*)d_in[2];  // (128, 1)
    float* out = (float*)d_out;

    const int batch = in_sizes[0] / K;          // 1048576
    const int grid  = batch / TILE_ROWS;        // 16384

    const size_t smem_bytes = (size_t)(K * WPAD + TILE_ROWS * K) * sizeof(float); // 100352 B

    // Needed for >48KB dynamic smem; host-side attribute set, not a stream op,
    // legal under graph capture and allocation-free.
    cudaFuncSetAttribute(linear128_fp32_kernel,
                         cudaFuncAttributeMaxDynamicSharedMemorySize,
                         (int)smem_bytes);

    linear128_fp32_kernel<<<grid, THREADS, smem_bytes>>>(x, W, bias, out);
}

// round 3
// speedup vs baseline: 3.6090x; 3.6090x over previous
#include <cuda_runtime.h>
#include <cuda_bf16.h>
#include <cstdint>

// out[b][o] = sum_k x[b][k] * W[o][k] + bias[o]
// x: (1048576,128) f32, W: (128,128) f32, bias: (128,1), out f32.
//
// bf16-split mma.sync GEMM (sm_103 base target; tcgen05 unavailable in this
// toolchain -- ptxas targets sm_103 without the 'a' feature set).
//   x = xh + xl (bf16), W = wh + wl (bf16)
//   D = xh*wh + xh*wl + xl*wh   (fp32 accum; dropped lo*lo ~ 2^-16 rel err)
// A = x (row-major), B = W[o][k] row-major -> plain ldmatrix gives B frag.
// Persistent CTAs, CTA tile 128x128, warp tile 32x64, double-buffered x smem.

#define THREADS 256
#define KDIM    128
#define TILE_B  128

// smem: x tiles [buf][part] 32KB each at 0..128K; W [part] at 128K..192K
#define XS_OFF(b,p) ((((b)*2)+(p))*32768)
#define WS_OFF(p)   (131072 + (p)*32768)
#define SMEM_BYTES  196608

// ---------------- helpers ----------------
__device__ __forceinline__ uint32_t smem_u32(const void* p) {
    uint32_t a;
    asm("{ .reg .u64 t; cvta.to.shared.u64 t, %1; cvt.u32.u64 %0, t; }" : "=r"(a) : "l"(p));
    return a;
}
__device__ __forceinline__ void sts64(uint32_t addr, uint32_t a, uint32_t b) {
    asm volatile("st.shared.v2.b32 [%0], {%1,%2};" :: "r"(addr), "r"(a), "r"(b));
}
__device__ __forceinline__ void ldsm4(uint32_t r[4], uint32_t addr) {
    asm volatile("ldmatrix.sync.aligned.m8n8.x4.shared.b16 {%0,%1,%2,%3}, [%4];"
                 : "=r"(r[0]), "=r"(r[1]), "=r"(r[2]), "=r"(r[3]) : "r"(addr));
}
__device__ __forceinline__ void hmma(float* d, const uint32_t a[4], uint32_t b0, uint32_t b1) {
    asm volatile("mma.sync.aligned.m16n8k16.row.col.f32.bf16.bf16.f32 "
                 "{%0,%1,%2,%3}, {%4,%5,%6,%7}, {%8,%9}, {%0,%1,%2,%3};"
                 : "+f"(d[0]), "+f"(d[1]), "+f"(d[2]), "+f"(d[3])
                 : "r"(a[0]), "r"(a[1]), "r"(a[2]), "r"(a[3]), "r"(b0), "r"(b1));
}
// split a float pair into bf16x2 hi and bf16x2 lo
__device__ __forceinline__ void cvt_pair(float xx, float yy, uint32_t& h, uint32_t& l) {
    __nv_bfloat162 hb = __float22bfloat162_rn(make_float2(xx, yy));
    float2 hf = __bfloat1622float2(hb);
    __nv_bfloat162 lb = __float22bfloat162_rn(make_float2(xx - hf.x, yy - hf.y));
    h = *reinterpret_cast<uint32_t*>(&hb);
    l = *reinterpret_cast<uint32_t*>(&lb);
}

// swizzled byte offset inside a 128-row x 256B tile: row*256 + (kb ^ ((row&7)<<4))
__device__ __forceinline__ uint32_t swz(int row, uint32_t kb) {
    return (uint32_t)row * 256u + (kb ^ (uint32_t)((row & 7) << 4));
}

// ---- staging: 8 float4 per thread per batch (2 batches = full 128x128 tile) ----
__device__ __forceinline__ void ldg_batch(const float4* __restrict__ src, int tid, int j,
                                          float4 st[8]) {
    #pragma unroll
    for (int it = 0; it < 8; ++it) st[it] = src[tid + (j * 8 + it) * THREADS];
}
__device__ __forceinline__ void sts_batch(uint32_t xh, uint32_t xl, int tid, int j,
                                          const float4 st[8]) {
    #pragma unroll
    for (int it = 0; it < 8; ++it) {
        int fidx = tid + (j * 8 + it) * THREADS;   // float4 index in 128x(128/4)
        int row = fidx >> 5;
        int g4  = fidx & 31;
        uint32_t off = swz(row, (uint32_t)(g4 * 8));
        uint32_t h0, l0, h1, l1;
        cvt_pair(st[it].x, st[it].y, h0, l0);
        cvt_pair(st[it].z, st[it].w, h1, l1);
        sts64(xh + off, h0, h1);
        sts64(xl + off, l0, l1);
    }
}

// ---- one GEMM pass: D += A(xbase) * B(wbase)^T over K=128 ----
__device__ __forceinline__ void gemm_pass(uint32_t xbase, uint32_t wbase,
                                          const uint32_t a_ro[2], const uint32_t a_sw[2], uint32_t a_kb,
                                          const uint32_t b_ro[4], const uint32_t b_sw[4], uint32_t b_kb,
                                          float d[2][8][4]) {
    #pragma unroll
    for (int ks = 0; ks < 8; ++ks) {
        const uint32_t kbyte = (uint32_t)(ks * 32);
        uint32_t a[2][4];
        #pragma unroll
        for (int mf = 0; mf < 2; ++mf)
            ldsm4(a[mf], xbase + a_ro[mf] + ((kbyte + a_kb) ^ a_sw[mf]));
        uint32_t b0[8], b1[8];
        #pragma unroll
        for (int q = 0; q < 4; ++q) {
            uint32_t r[4];
            ldsm4(r, wbase + b_ro[q] + ((kbyte + b_kb) ^ b_sw[q]));
            b0[2 * q] = r[0]; b1[2 * q] = r[1];
            b0[2 * q + 1] = r[2]; b1[2 * q + 1] = r[3];
        }
        #pragma unroll
        for (int mf = 0; mf < 2; ++mf)
            #pragma unroll
            for (int nf = 0; nf < 8; ++nf)
                hmma(d[mf][nf], a[mf], b0[nf], b1[nf]);
    }
}

__global__ __launch_bounds__(THREADS, 1)
void linear128_mma_kernel(const float* __restrict__ x,
                          const float* __restrict__ W,
                          const float* __restrict__ bias,
                          float* __restrict__ out,
                          int ntiles)
{
    extern __shared__ __align__(1024) char smem[];
    const uint32_t sb  = smem_u32(smem);
    const uint32_t wsh = sb + WS_OFF(0);
    const uint32_t wsl = sb + WS_OFF(1);

    const int tid  = threadIdx.x;
    const int lane = tid & 31;
    const int wid  = tid >> 5;
    const int mg   = wid >> 1;   // 0..3: batch rows 32*mg
    const int ng   = wid & 1;    // 0..1: out cols 64*ng

    // ---- stage W hi/lo into smem (once) ----
    {
        const float4* W4 = (const float4*)W;
        #pragma unroll
        for (int it = 0; it < 16; ++it) {
            int fidx = tid + it * THREADS;
            int row = fidx >> 5;
            int g4  = fidx & 31;
            float4 v = W4[fidx];
            uint32_t off = swz(row, (uint32_t)(g4 * 8));
            uint32_t h0, l0, h1, l1;
            cvt_pair(v.x, v.y, h0, l0);
            cvt_pair(v.z, v.w, h1, l1);
            sts64(wsh + off, h0, h1);
            sts64(wsl + off, l0, l1);
        }
    }

    // ---- bias fragment (float2 per nfrag) ----
    float2 bv[8];
    #pragma unroll
    for (int nf = 0; nf < 8; ++nf)
        bv[nf] = *(const float2*)(bias + ng * 64 + nf * 8 + (lane & 3) * 2);

    // ---- per-thread ldmatrix address components ----
    uint32_t a_ro[2], a_sw[2];
    #pragma unroll
    for (int mf = 0; mf < 2; ++mf) {
        int r = mg * 32 + mf * 16 + ((lane >> 3) & 1) * 8 + (lane & 7);
        a_ro[mf] = (uint32_t)r * 256u;
        a_sw[mf] = (uint32_t)((r & 7) << 4);
    }
    const uint32_t a_kb = (uint32_t)((lane >> 4) * 16);
    uint32_t b_ro[4], b_sw[4];
    #pragma unroll
    for (int q = 0; q < 4; ++q) {
        int r = ng * 64 + q * 16 + ((lane >> 4) << 3) + (lane & 7);
        b_ro[q] = (uint32_t)r * 256u;
        b_sw[q] = (uint32_t)((r & 7) << 4);
    }
    const uint32_t b_kb = (uint32_t)(((lane >> 3) & 1) * 16);

    const int bid  = blockIdx.x;
    const int grid = gridDim.x;
    const float4* x4 = (const float4*)x;

    // ---- prologue: stage x tile(bid) into buf 0 ----
    if (bid < ntiles) {
        float4 st[8];
        ldg_batch(x4 + (size_t)bid * 4096, tid, 0, st);
        sts_batch(sb + XS_OFF(0, 0), sb + XS_OFF(0, 1), tid, 0, st);
        ldg_batch(x4 + (size_t)bid * 4096, tid, 1, st);
        sts_batch(sb + XS_OFF(0, 0), sb + XS_OFF(0, 1), tid, 1, st);
    }
    __syncthreads();

    int i = 0;
    for (int tile = bid; tile < ntiles; tile += grid, ++i) {
        const int b = i & 1;
        const uint32_t xh  = sb + XS_OFF(b, 0);
        const uint32_t xl  = sb + XS_OFF(b, 1);
        const uint32_t nxh = sb + XS_OFF(1 - b, 0);
        const uint32_t nxl = sb + XS_OFF(1 - b, 1);
        const bool hn = (tile + grid) < ntiles;
        const float4* nsrc = x4 + (size_t)(tile + grid) * 4096;

        float d[2][8][4];
        #pragma unroll
        for (int mf = 0; mf < 2; ++mf)
            #pragma unroll
            for (int nf = 0; nf < 8; ++nf)
                #pragma unroll
                for (int e = 0; e < 4; ++e) d[mf][nf][e] = 0.0f;

        float4 st[8];
        if (hn) ldg_batch(nsrc, tid, 0, st);           // LDG hidden under pass 1

        gemm_pass(xh, wsh, a_ro, a_sw, a_kb, b_ro, b_sw, b_kb, d);   // xh*wh

        if (hn) { sts_batch(nxh, nxl, tid, 0, st); ldg_batch(nsrc, tid, 1, st); }

        gemm_pass(xh, wsl, a_ro, a_sw, a_kb, b_ro, b_sw, b_kb, d);   // xh*wl

        if (hn) sts_batch(nxh, nxl, tid, 1, st);

        gemm_pass(xl, wsh, a_ro, a_sw, a_kb, b_ro, b_sw, b_kb, d);   // xl*wh

        // ---- epilogue: D frag (row=lane>>2 (+8), col=2*(lane&3)+{0,1}) ----
        #pragma unroll
        for (int mf = 0; mf < 2; ++mf) {
            const size_t rbase =
                ((size_t)tile * TILE_B + (size_t)(mg * 32 + mf * 16 + (lane >> 2))) * 128;
            #pragma unroll
            for (int nf = 0; nf < 8; ++nf) {
                const int col = ng * 64 + nf * 8 + (lane & 3) * 2;
                float2 v0, v1;
                v0.x = d[mf][nf][0] + bv[nf].x;
                v0.y = d[mf][nf][1] + bv[nf].y;
                v1.x = d[mf][nf][2] + bv[nf].x;
                v1.y = d[mf][nf][3] + bv[nf].y;
                *(float2*)(out + rbase + col)           = v0;
                *(float2*)(out + rbase + 8 * 128 + col) = v1;
            }
        }
        __syncthreads();
    }
}

extern "C" void kernel_launch(void* const* d_in, const int* in_sizes, int n_in,
                              void* d_out, int out_size)
{
    const float* x    = (const float*)d_in[0];
    const float* W    = (const float*)d_in[1];
    const float* bias = (const float*)d_in[2];
    float* out = (float*)d_out;

    const int batch  = in_sizes[0] / KDIM;   // 1048576
    const int ntiles = batch / TILE_B;       // 8192

    int sms = 148;
    cudaDeviceGetAttribute(&sms, cudaDevAttrMultiProcessorCount, 0);
    if (sms <= 0) sms = 148;
    int grid = sms < ntiles ? sms : ntiles;

    cudaFuncSetAttribute(linear128_mma_kernel,
                         cudaFuncAttributeMaxDynamicSharedMemorySize, SMEM_BYTES);

    linear128_mma_kernel<<<grid, THREADS, SMEM_BYTES>>>(x, W, bias, out, ntiles);
}